// round 12
// baseline (speedup 1.0000x reference)
#include <cuda_runtime.h>
#include <math.h>
#include <float.h>

#define BB 8
#define CC 64
#define HH 62
#define TT 400
#define HT (HH*TT)            // 24800
#define NTOT (BB*CC*HT)       // 12697600
#define SSZ 32
#define MIDC 4
#define NBLK 194              // ceil(HT/128)

typedef unsigned long long u64;

__device__ __forceinline__ u64 ffma2(u64 a, u64 b, u64 c) {
    u64 d;
    asm("fma.rn.f32x2 %0, %1, %2, %3;" : "=l"(d) : "l"(a), "l"(b), "l"(c));
    return d;
}
__device__ __forceinline__ u64 bcast2(float x) {
    u64 r;
    asm("mov.b64 %0, {%1, %1};" : "=l"(r) : "f"(x));
    return r;
}
__device__ __forceinline__ u64 pack2(float lo, float hi) {
    u64 r;
    asm("mov.b64 %0, {%1, %2};" : "=l"(r) : "f"(lo), "f"(hi));
    return r;
}
__device__ __forceinline__ void unpack2(u64 v, float& lo, float& hi) {
    asm("mov.b64 {%0, %1}, %2;" : "=f"(lo), "=f"(hi) : "l"(v));
}

// ---------------- scratch (device globals) ----------------
__device__ float g_A[NTOT];
__device__ float g_B2[NTOT];
__device__ float g_C2[NTOT];
__device__ float g_D2[NTOT];
__device__ float g_E2[NTOT];
__device__ float g_ach[BB*CC];
__device__ float g_cps[BB*NBLK*CC];
__device__ float g_cpm[BB*NBLK*CC];
__device__ float g_sp[BB*2*HT];
__device__ float g_asp[BB*HT];
__device__ float g_sc[2*TT*CC];
__device__ float g_Wt[8*CC*CC];       // transposed weights [m][c][o]

// ---------------- transpose all 8 pointwise weight matrices --------------------
__global__ void wtrans(const float* __restrict__ in_w, const float* __restrict__ dwpw,
                       const float* __restrict__ d1pw, const float* __restrict__ out_w,
                       float* __restrict__ Wt)
{
    int m = blockIdx.x;
    const float* src = (m == 0) ? in_w
                     : (m < 5)  ? dwpw + (m-1)*CC*CC
                     : (m < 7)  ? d1pw + (m-5)*CC*CC
                                : out_w;
    for (int i = threadIdx.x; i < CC*CC; i += 256) {
        int o = i >> 6, c = i & 63;
        Wt[m*CC*CC + c*CC + o] = src[i];
    }
}

// ============ register-blocked pointwise 64x64 mix, f32x2 over out-pairs ======
template<int ACT, bool SPSTATS, bool CPARTS>
__launch_bounds__(256, 3)
__global__ void pw2(const float* __restrict__ in, const float* __restrict__ Wt,
                    const float* __restrict__ gamma, const float* __restrict__ beta,
                    float* __restrict__ out, float* __restrict__ sp,
                    float* __restrict__ cps, float* __restrict__ cpm)
{
    extern __shared__ float sm[];
    float* sWt = sm;                   // 4096 floats, [c][o]
    float* sx  = sm + 4096;            // 64*128 floats
    float* sredS = sm + 4096 + 8192;   // 8*128 (SPSTATS)
    float* sredM = sredS + 1024;

    int tid = threadIdx.x;
    int px = tid & 31, oy = tid >> 5;
    int b = blockIdx.y;
    int pos0 = blockIdx.x * 128;
    const float* inb = in + (size_t)b*CC*HT;

    #pragma unroll
    for (int i = tid; i < 1024; i += 256)
        ((float4*)sWt)[i] = ((const float4*)Wt)[i];

    #pragma unroll
    for (int i = tid; i < 2048; i += 256) {
        int c = i >> 5, j = i & 31;
        int gp = pos0 + j*4;
        float4 v = make_float4(0.f,0.f,0.f,0.f);
        if (gp + 3 < HT) {
            v = *(const float4*)(inb + (size_t)c*HT + gp);
        } else {
            float tmp[4] = {0,0,0,0};
            for (int k = 0; k < 4; k++) if (gp+k < HT) tmp[k] = inb[(size_t)c*HT + gp + k];
            v = make_float4(tmp[0],tmp[1],tmp[2],tmp[3]);
        }
        *(float4*)(sx + c*128 + j*4) = v;
    }
    __syncthreads();

    int p = px*4;
    u64 acc2[4][4];
    #pragma unroll
    for (int q = 0; q < 4; q++)
        #pragma unroll
        for (int k = 0; k < 4; k++) acc2[q][k] = 0ull;

    #pragma unroll
    for (int c4 = 0; c4 < 16; c4++) {
        #pragma unroll
        for (int cc = 0; cc < 4; cc++) {
            int c = c4*4 + cc;
            float4 xv = *(const float4*)(sx + c*128 + p);
            u64 xp0 = bcast2(xv.x), xp1 = bcast2(xv.y);
            u64 xp2 = bcast2(xv.z), xp3 = bcast2(xv.w);
            const ulonglong2* wrow = (const ulonglong2*)(sWt + c*64 + oy*8);
            ulonglong2 wa = wrow[0];
            ulonglong2 wb = wrow[1];
            acc2[0][0] = ffma2(wa.x, xp0, acc2[0][0]);
            acc2[0][1] = ffma2(wa.x, xp1, acc2[0][1]);
            acc2[0][2] = ffma2(wa.x, xp2, acc2[0][2]);
            acc2[0][3] = ffma2(wa.x, xp3, acc2[0][3]);
            acc2[1][0] = ffma2(wa.y, xp0, acc2[1][0]);
            acc2[1][1] = ffma2(wa.y, xp1, acc2[1][1]);
            acc2[1][2] = ffma2(wa.y, xp2, acc2[1][2]);
            acc2[1][3] = ffma2(wa.y, xp3, acc2[1][3]);
            acc2[2][0] = ffma2(wb.x, xp0, acc2[2][0]);
            acc2[2][1] = ffma2(wb.x, xp1, acc2[2][1]);
            acc2[2][2] = ffma2(wb.x, xp2, acc2[2][2]);
            acc2[2][3] = ffma2(wb.x, xp3, acc2[2][3]);
            acc2[3][0] = ffma2(wb.y, xp0, acc2[3][0]);
            acc2[3][1] = ffma2(wb.y, xp1, acc2[3][1]);
            acc2[3][2] = ffma2(wb.y, xp2, acc2[3][2]);
            acc2[3][3] = ffma2(wb.y, xp3, acc2[3][3]);
        }
    }

    float rr[8][4];
    #pragma unroll
    for (int q = 0; q < 4; q++)
        #pragma unroll
        for (int k = 0; k < 4; k++)
            unpack2(acc2[q][k], rr[2*q][k], rr[2*q+1][k]);

    int gp0 = pos0 + p;
    bool full = (gp0 + 3) < HT;
    float* outb = out + (size_t)b*CC*HT;
    float psum[4] = {0,0,0,0};
    float pmax[4] = {-FLT_MAX,-FLT_MAX,-FLT_MAX,-FLT_MAX};
    #pragma unroll
    for (int o8 = 0; o8 < 8; o8++) {
        int o = oy*8 + o8;
        float r[4];
        #pragma unroll
        for (int k = 0; k < 4; k++) r[k] = rr[o8][k];
        if (gamma) {
            float g = __ldg(gamma + o), be = __ldg(beta + o);
            #pragma unroll
            for (int k = 0; k < 4; k++) r[k] = fmaf(r[k], g, be);
        }
        #pragma unroll
        for (int k = 0; k < 4; k++) {
            if (ACT == 1) r[k] = fmaxf(r[k], 0.f);
            if (ACT == 2) r[k] = 1.f/(1.f + expf(-r[k]));
        }
        if (SPSTATS) {
            #pragma unroll
            for (int k = 0; k < 4; k++) { psum[k] += r[k]; pmax[k] = fmaxf(pmax[k], r[k]); }
        }
        if (CPARTS) {
            float ps = 0.f, pm = -FLT_MAX;
            #pragma unroll
            for (int k = 0; k < 4; k++)
                if (gp0 + k < HT) { ps += r[k]; pm = fmaxf(pm, r[k]); }
            #pragma unroll
            for (int s = 16; s > 0; s >>= 1) {
                ps += __shfl_xor_sync(0xffffffffu, ps, s);
                pm = fmaxf(pm, __shfl_xor_sync(0xffffffffu, pm, s));
            }
            if (px == 0) {
                cps[((size_t)b*NBLK + blockIdx.x)*CC + o] = ps;
                cpm[((size_t)b*NBLK + blockIdx.x)*CC + o] = pm;
            }
        }
        if (full) {
            *(float4*)(outb + (size_t)o*HT + gp0) = make_float4(r[0],r[1],r[2],r[3]);
        } else {
            for (int k = 0; k < 4; k++) if (gp0+k < HT) outb[(size_t)o*HT + gp0 + k] = r[k];
        }
    }

    if (SPSTATS) {
        #pragma unroll
        for (int k = 0; k < 4; k++) { sredS[oy*128 + p + k] = psum[k]; sredM[oy*128 + p + k] = pmax[k]; }
        __syncthreads();
        if (tid < 128) {
            float s = 0.f, m = -FLT_MAX;
            #pragma unroll
            for (int g = 0; g < 8; g++) { s += sredS[g*128 + tid]; m = fmaxf(m, sredM[g*128 + tid]); }
            int gp = pos0 + tid;
            if (gp < HT) {
                sp[(size_t)b*2*HT + gp]      = s*(1.f/CC);
                sp[(size_t)b*2*HT + HT + gp] = m;
            }
        }
    }
}

// ============ fused dw1x3(b1^2 * a_ch) + pointwise + bn + sigmoid (f32x2) ===
// Phase A vectorized: float4 core tile (pitch 128) + left/right halo arrays.
// smem floats: score@0 (8192) | sleft@8192 (64) | sright@8256 (64) | sx@8448 (8192)
// sWt overlays score region after conv phase.
__launch_bounds__(256, 3)
__global__ void cb_fused(const float* __restrict__ b1, const float* __restrict__ ach,
                         const float* __restrict__ dw, const float* __restrict__ Wt,
                         const float* __restrict__ gamma, const float* __restrict__ beta,
                         float* __restrict__ out)
{
    extern __shared__ float sm[];
    float* score  = sm;            // 64*128
    float* sleft  = sm + 8192;     // 64
    float* sright = sm + 8256;     // 64
    float* sWt    = sm;            // union (after conv phase), 4096 floats
    float* sx     = sm + 8448;     // 64*128

    int tid = threadIdx.x;
    int px = tid & 31, oy = tid >> 5;
    int b = blockIdx.y;
    int pos0 = blockIdx.x * 128;
    const float* inb = b1 + (size_t)b*CC*HT;

    // phase A: core tile f = v^2*a, float4
    #pragma unroll
    for (int i = tid; i < 2048; i += 256) {
        int c = i >> 5, j = i & 31;
        int gp = pos0 + j*4;
        float a = __ldg(ach + b*CC + c);
        float4 v;
        if (gp + 3 < HT) {
            v = *(const float4*)(inb + (size_t)c*HT + gp);
        } else {
            float tmp[4] = {0,0,0,0};
            for (int k = 0; k < 4; k++) if (gp+k < HT) tmp[k] = inb[(size_t)c*HT + gp + k];
            v = make_float4(tmp[0],tmp[1],tmp[2],tmp[3]);
        }
        *(float4*)(score + c*128 + j*4) =
            make_float4(v.x*v.x*a, v.y*v.y*a, v.z*v.z*a, v.w*v.w*a);
    }
    // halo columns
    if (tid < 64) {
        int c = tid;
        float a = __ldg(ach + b*CC + c);
        float lv = 0.f, rv = 0.f;
        if (pos0 > 0)           { float q = inb[(size_t)c*HT + pos0 - 1];   lv = q*q*a; }
        if (pos0 + 128 < HT)    { float q = inb[(size_t)c*HT + pos0 + 128]; rv = q*q*a; }
        sleft[c] = lv; sright[c] = rv;
    }
    __syncthreads();

    // phase B: 1x3 conv along t into sx
    for (int i = tid; i < 8192; i += 256) {
        int c = i >> 7, j = i & 127;
        int gp = pos0 + j;
        float r = 0.f;
        if (gp < HT) {
            int t = gp - (gp/TT)*TT;
            float w0 = __ldg(dw + c*3), w1 = __ldg(dw + c*3 + 1), w2 = __ldg(dw + c*3 + 2);
            r = w1 * score[c*128 + j];
            if (t > 0)    r = fmaf(w0, (j > 0)   ? score[c*128 + j - 1] : sleft[c],  r);
            if (t < TT-1) r = fmaf(w2, (j < 127) ? score[c*128 + j + 1] : sright[c], r);
        }
        sx[c*128 + j] = r;
    }
    __syncthreads();

    #pragma unroll
    for (int i = tid; i < 1024; i += 256)
        ((float4*)sWt)[i] = ((const float4*)Wt)[i];
    __syncthreads();

    int p = px*4;
    u64 acc2[4][4];
    #pragma unroll
    for (int q = 0; q < 4; q++)
        #pragma unroll
        for (int k = 0; k < 4; k++) acc2[q][k] = 0ull;

    #pragma unroll
    for (int c4 = 0; c4 < 16; c4++) {
        #pragma unroll
        for (int cc = 0; cc < 4; cc++) {
            int c = c4*4 + cc;
            float4 xv = *(const float4*)(sx + c*128 + p);
            u64 xp0 = bcast2(xv.x), xp1 = bcast2(xv.y);
            u64 xp2 = bcast2(xv.z), xp3 = bcast2(xv.w);
            const ulonglong2* wrow = (const ulonglong2*)(sWt + c*64 + oy*8);
            ulonglong2 wa = wrow[0];
            ulonglong2 wb = wrow[1];
            acc2[0][0] = ffma2(wa.x, xp0, acc2[0][0]);
            acc2[0][1] = ffma2(wa.x, xp1, acc2[0][1]);
            acc2[0][2] = ffma2(wa.x, xp2, acc2[0][2]);
            acc2[0][3] = ffma2(wa.x, xp3, acc2[0][3]);
            acc2[1][0] = ffma2(wa.y, xp0, acc2[1][0]);
            acc2[1][1] = ffma2(wa.y, xp1, acc2[1][1]);
            acc2[1][2] = ffma2(wa.y, xp2, acc2[1][2]);
            acc2[1][3] = ffma2(wa.y, xp3, acc2[1][3]);
            acc2[2][0] = ffma2(wb.x, xp0, acc2[2][0]);
            acc2[2][1] = ffma2(wb.x, xp1, acc2[2][1]);
            acc2[2][2] = ffma2(wb.x, xp2, acc2[2][2]);
            acc2[2][3] = ffma2(wb.x, xp3, acc2[2][3]);
            acc2[3][0] = ffma2(wb.y, xp0, acc2[3][0]);
            acc2[3][1] = ffma2(wb.y, xp1, acc2[3][1]);
            acc2[3][2] = ffma2(wb.y, xp2, acc2[3][2]);
            acc2[3][3] = ffma2(wb.y, xp3, acc2[3][3]);
        }
    }

    float rr[8][4];
    #pragma unroll
    for (int q = 0; q < 4; q++)
        #pragma unroll
        for (int k = 0; k < 4; k++)
            unpack2(acc2[q][k], rr[2*q][k], rr[2*q+1][k]);

    int gp0 = pos0 + p;
    bool full = (gp0 + 3) < HT;
    float* outb = out + (size_t)b*CC*HT;
    #pragma unroll
    for (int o8 = 0; o8 < 8; o8++) {
        int o = oy*8 + o8;
        float g = __ldg(gamma + o), be = __ldg(beta + o);
        float r[4];
        #pragma unroll
        for (int k = 0; k < 4; k++) {
            r[k] = fmaf(rr[o8][k], g, be);
            r[k] = 1.f/(1.f + expf(-r[k]));
        }
        if (full) *(float4*)(outb + (size_t)o*HT + gp0) = make_float4(r[0],r[1],r[2],r[3]);
        else for (int k = 0; k < 4; k++) if (gp0+k < HT) outb[(size_t)o*HT + gp0 + k] = r[k];
    }
}

// ========= dual depthwise 5x5: 64t x 16h tiles, 4 outputs/thread, f32x2 ========
__launch_bounds__(256)
__global__ void dw5_dual2(const float* __restrict__ in, const float* __restrict__ w0,
                          const float* __restrict__ w1,
                          float* __restrict__ out0, float* __restrict__ out1, int rev)
{
    int bc = blockIdx.z;
    int c  = bc & (CC-1);
    __shared__ float tile[20*68];
    __shared__ u64 swp[25];
    int t0 = blockIdx.x*64 - 2;
    int h0 = blockIdx.y*16 - 2;
    const float* base = in + (size_t)bc*HT;
    int tid = threadIdx.x;

    if (tid < 25) swp[tid] = pack2(__ldg(w0 + c*25 + tid), __ldg(w1 + c*25 + tid));

    for (int i = tid; i < 20*68; i += 256) {
        int hh = i / 68, tt = i - hh*68;
        int h = h0 + hh, t = t0 + tt;
        float v = 0.f;
        if (h >= 0 && h < HH && t >= 0 && t < TT) {
            int tr = rev ? (TT-1-t) : t;
            v = base[h*TT + tr];
        }
        tile[i] = v;
    }
    __syncthreads();

    int tt0 = (tid & 15)*4;
    int hh  = tid >> 4;
    int tg  = blockIdx.x*64 + tt0;
    int hg  = blockIdx.y*16 + hh;

    u64 acc[4] = {0ull, 0ull, 0ull, 0ull};
    #pragma unroll
    for (int kh = 0; kh < 5; kh++) {
        const float* row = tile + (hh + kh)*68 + tt0;
        float4 ra = *(const float4*)(row);
        float4 rb = *(const float4*)(row + 4);
        u64 br[8];
        br[0] = bcast2(ra.x); br[1] = bcast2(ra.y);
        br[2] = bcast2(ra.z); br[3] = bcast2(ra.w);
        br[4] = bcast2(rb.x); br[5] = bcast2(rb.y);
        br[6] = bcast2(rb.z); br[7] = bcast2(rb.w);
        #pragma unroll
        for (int kw = 0; kw < 5; kw++) {
            u64 w = swp[kh*5 + kw];
            acc[0] = ffma2(w, br[kw+0], acc[0]);
            acc[1] = ffma2(w, br[kw+1], acc[1]);
            acc[2] = ffma2(w, br[kw+2], acc[2]);
            acc[3] = ffma2(w, br[kw+3], acc[3]);
        }
    }

    if (hg >= HH) return;
    float o0[4], o1[4];
    #pragma unroll
    for (int k = 0; k < 4; k++) unpack2(acc[k], o0[k], o1[k]);
    size_t obase = (size_t)bc*HT + hg*TT + tg;
    if (tg + 3 < TT) {
        *(float4*)(out0 + obase) = make_float4(o0[0], o0[1], o0[2], o0[3]);
        *(float4*)(out1 + obase) = make_float4(o1[0], o1[1], o1[2], o1[3]);
    } else {
        for (int k = 0; k < 4; k++) if (tg + k < TT) {
            out0[obase + k] = o0[k];
            out1[obase + k] = o1[k];
        }
    }
}

// ---------------- channel attention: reduce partials + MLP ---------------------
__global__ void chan_attn2(const float* __restrict__ cps, const float* __restrict__ cpm,
                           const float* __restrict__ w1, const float* __restrict__ w2,
                           float* __restrict__ a)
{
    int b = blockIdx.x, tid = threadIdx.x;
    __shared__ float sa[CC], smx[CC], hs[MIDC];
    int c = tid >> 2, q = tid & 3;
    float s = 0.f, m = -FLT_MAX;
    for (int k = q; k < NBLK; k += 4) {
        s += cps[((size_t)b*NBLK + k)*CC + c];
        m = fmaxf(m, cpm[((size_t)b*NBLK + k)*CC + c]);
    }
    s += __shfl_xor_sync(0xffffffffu, s, 1);
    m = fmaxf(m, __shfl_xor_sync(0xffffffffu, m, 1));
    s += __shfl_xor_sync(0xffffffffu, s, 2);
    m = fmaxf(m, __shfl_xor_sync(0xffffffffu, m, 2));
    if (q == 0) { sa[c] = s*(1.f/(float)HT); smx[c] = m; }
    __syncthreads();
    if (tid < MIDC) {
        float ha = 0.f, hm = 0.f;
        for (int k = 0; k < CC; k++) {
            ha = fmaf(sa[k],  w1[tid*CC + k], ha);
            hm = fmaf(smx[k], w1[tid*CC + k], hm);
        }
        hs[tid] = fmaxf(ha, 0.f) + fmaxf(hm, 0.f);
    }
    __syncthreads();
    if (tid < CC) {
        float acc = 0.f;
        #pragma unroll
        for (int j = 0; j < MIDC; j++) acc = fmaf(hs[j], w2[tid*MIDC + j], acc);
        a[b*CC + tid] = 1.f/(1.f + expf(-acc));
    }
}

// ---------------- spatial attention 7x7 conv (2ch->1) + sigmoid -----------------
__global__ void spat_conv(const float* __restrict__ sp, const float* __restrict__ w,
                          float* __restrict__ asp)
{
    int t = blockIdx.x*32 + threadIdx.x;
    int h = blockIdx.y*8  + threadIdx.y;
    int b = blockIdx.z;
    if (t >= TT || h >= HH) return;
    float acc = 0.f;
    #pragma unroll
    for (int ci = 0; ci < 2; ci++) {
        const float* base = sp + ((size_t)b*2 + ci)*HT;
        #pragma unroll
        for (int kh = 0; kh < 7; kh++) {
            int hh = h + kh - 3;
            if (hh < 0 || hh >= HH) continue;
            #pragma unroll
            for (int kw = 0; kw < 7; kw++) {
                int tt = t + kw - 3;
                if (tt < 0 || tt >= TT) continue;
                acc = fmaf(base[hh*TT + tt], __ldg(&w[ci*49 + kh*7 + kw]), acc);
            }
        }
    }
    asp[(size_t)b*HT + h*TT + t] = 1.f/(1.f + expf(-acc));
}

// ---------------- SSM precompute: log-depth chain via A^8 ----------------------
#define SSM_SMEM ((5152 + TT*SSZ)*4)
__launch_bounds__(256)
__global__ void ssm_pre3(const float* __restrict__ A, const float* __restrict__ Bv,
                         const float* __restrict__ Cm, float* __restrict__ sc)
{
    extern __shared__ float sm[];
    float* sA  = sm;
    float* sM  = sm + 1024;
    float* sT  = sm + 2048;
    float* sC  = sm + 3072;
    float* sVV = sm + 5120;
    float* sS  = sm + 5152;

    int half = blockIdx.x;
    A  += half*SSZ*SSZ;
    Bv += half*SSZ;
    Cm += half*SSZ*CC;
    sc += (size_t)half*TT*CC;

    int tid = threadIdx.x;
    int wid = tid >> 5, lid = tid & 31;

    for (int i = tid; i < 1024; i += 256) sA[i] = A[i];
    for (int i = tid; i < 2048; i += 256) sC[i] = Cm[i];
    __syncthreads();
    for (int i = tid; i < 1024; i += 256) {
        int r = i >> 5, c = i & 31;
        float acc = 0.f;
        #pragma unroll
        for (int k = 0; k < 32; k++) acc = fmaf(sA[r*32+k], sA[k*32+c], acc);
        sT[i] = acc;
    }
    __syncthreads();
    for (int i = tid; i < 1024; i += 256) {
        int r = i >> 5, c = i & 31;
        float acc = 0.f;
        #pragma unroll
        for (int k = 0; k < 32; k++) acc = fmaf(sT[r*32+k], sT[k*32+c], acc);
        sM[i] = acc;
    }
    __syncthreads();
    for (int i = tid; i < 1024; i += 256) {
        int r = i >> 5, c = i & 31;
        float acc = 0.f;
        #pragma unroll
        for (int k = 0; k < 32; k++) acc = fmaf(sM[r*32+k], sM[k*32+c], acc);
        sT[i] = acc;
    }
    __syncthreads();

    if (wid == 0) {
        float bv = Bv[lid];
        float Arow[32];
        #pragma unroll
        for (int j = 0; j < 32; j++) Arow[j] = sA[lid*32 + j];
        float x = bv;
        sS[lid] = x;
        #pragma unroll
        for (int k = 1; k < 8; k++) {
            float nx = bv;
            #pragma unroll
            for (int j = 0; j < 32; j++) nx = fmaf(__shfl_sync(0xffffffffu, x, j), Arow[j], nx);
            x = nx;
            sS[k*32 + lid] = x;
        }
        sVV[lid] = x;
    }
    __syncthreads();

    {
        float Mrow[32];
        #pragma unroll
        for (int j = 0; j < 32; j++) Mrow[j] = sT[lid*32 + j];
        float vv = sVV[lid];
        float x = sS[wid*32 + lid];
        for (int n = 1; n < 50; n++) {
            float p0 = vv, p1 = 0.f, p2 = 0.f, p3 = 0.f;
            #pragma unroll
            for (int j = 0; j < 8; j++) {
                p0 = fmaf(__shfl_sync(0xffffffffu, x, j),    Mrow[j],    p0);
                p1 = fmaf(__shfl_sync(0xffffffffu, x, j+8),  Mrow[j+8],  p1);
                p2 = fmaf(__shfl_sync(0xffffffffu, x, j+16), Mrow[j+16], p2);
                p3 = fmaf(__shfl_sync(0xffffffffu, x, j+24), Mrow[j+24], p3);
            }
            x = (p0 + p1) + (p2 + p3);
            sS[(wid + 8*n)*32 + lid] = x;
        }
    }
    __syncthreads();

    for (int i = tid; i < TT*CC; i += 256) {
        int t = i >> 6, c = i & 63;
        float acc = 0.f;
        #pragma unroll
        for (int k = 0; k < 32; k++) acc = fmaf(sS[t*32 + k], sC[k*64 + c], acc);
        sc[i] = acc;
    }
}

// ---------------- fused: residual-gelu + channel-LN + spatial gate (float4) -----
// Block: 128 positions, 4 per thread; val staged in smem; float4 tensor traffic.
// A 4-pos group never straddles a T row (TT % 4 == 0), so h/c2 are group-constant
// and the reversed store is a lane-swapped float4.
__launch_bounds__(256, 2)
__global__ void final_fuse(const float* __restrict__ cb, const float* __restrict__ b2,
                           const float* __restrict__ asp, const float* __restrict__ sc,
                           const float* __restrict__ Dv, const float* __restrict__ lg,
                           const float* __restrict__ lb, float* __restrict__ out, int revout)
{
    __shared__ float sval[64*128];     // 32KB
    __shared__ float sred[1024];
    __shared__ float smu[128], srs[128];
    __shared__ float sD[CC], slg[CC], slb[CC];

    int tid = threadIdx.x;
    int px = tid & 31, cy = tid >> 5;
    int b = blockIdx.y;
    int pos0 = blockIdx.x * 128;
    int p = px*4;
    int gp0 = pos0 + p;
    bool ok = (gp0 + 3) < HT;          // groups are fully in or fully out (HT % 4 == 0)
    if (tid < CC) { sD[tid] = Dv[tid]; slg[tid] = lg[tid]; slb[tid] = lb[tid]; }
    __syncthreads();

    int t = gp0 % TT, h = gp0 / TT;
    const float* cbb = cb + (size_t)b*CC*HT;
    const float* b2b = b2 + (size_t)b*CC*HT;
    const float* scp = sc + t*CC;

    float bvv[8][4];
    float psum[4] = {0.f, 0.f, 0.f, 0.f};
    #pragma unroll
    for (int k = 0; k < 8; k++) {
        int c = cy*8 + k;
        int c2 = (h - 2*c) & (CC-1);
        float4 xv = make_float4(0.f,0.f,0.f,0.f);
        float4 bv = make_float4(0.f,0.f,0.f,0.f);
        if (ok) {
            xv = *(const float4*)(cbb + (size_t)c*HT + gp0);
            bv = *(const float4*)(b2b + (size_t)c*HT + gp0);
        }
        bvv[k][0] = bv.x; bvv[k][1] = bv.y; bvv[k][2] = bv.z; bvv[k][3] = bv.w;
        float xx[4] = {xv.x, xv.y, xv.z, xv.w};
        float v4[4];
        #pragma unroll
        for (int j = 0; j < 4; j++) {
            float pre = __ldg(scp + j*CC + c2) + xx[j]*sD[c2];
            float gel = 0.5f*pre*(1.f + erff(pre*0.70710678118654752f));
            v4[j] = xx[j] + gel;
            psum[j] += v4[j];
        }
        *(float4*)(sval + c*128 + p) = make_float4(v4[0], v4[1], v4[2], v4[3]);
    }
    *(float4*)(sred + cy*128 + p) = make_float4(psum[0], psum[1], psum[2], psum[3]);
    __syncthreads();
    if (tid < 128) {
        float s = 0.f;
        #pragma unroll
        for (int g = 0; g < 8; g++) s += sred[g*128 + tid];
        smu[tid] = s*(1.f/CC);
    }
    __syncthreads();
    float mu[4] = {smu[p], smu[p+1], smu[p+2], smu[p+3]};
    float vp[4] = {0.f, 0.f, 0.f, 0.f};
    #pragma unroll
    for (int k = 0; k < 8; k++) {
        int c = cy*8 + k;
        float4 v = *(const float4*)(sval + c*128 + p);
        float d0 = v.x-mu[0], d1 = v.y-mu[1], d2 = v.z-mu[2], d3 = v.w-mu[3];
        vp[0] = fmaf(d0, d0, vp[0]); vp[1] = fmaf(d1, d1, vp[1]);
        vp[2] = fmaf(d2, d2, vp[2]); vp[3] = fmaf(d3, d3, vp[3]);
    }
    *(float4*)(sred + cy*128 + p) = make_float4(vp[0], vp[1], vp[2], vp[3]);
    __syncthreads();
    if (tid < 128) {
        float s = 0.f;
        #pragma unroll
        for (int g = 0; g < 8; g++) s += sred[g*128 + tid];
        srs[tid] = rsqrtf(s*(1.f/CC) + 1e-5f);
    }
    __syncthreads();
    if (!ok) return;

    float rstd[4] = {srs[p], srs[p+1], srs[p+2], srs[p+3]};
    float4 a4 = *(const float4*)(asp + (size_t)b*HT + gp0);
    float av[4] = {a4.x, a4.y, a4.z, a4.w};
    float* outb = out + (size_t)b*CC*HT;
    int obase = revout ? (h*TT + (TT-4-t)) : gp0;
    #pragma unroll
    for (int k = 0; k < 8; k++) {
        int c = cy*8 + k;
        float4 v = *(const float4*)(sval + c*128 + p);
        float vv4[4] = {v.x, v.y, v.z, v.w};
        float r[4];
        #pragma unroll
        for (int j = 0; j < 4; j++) {
            float y = (vv4[j]-mu[j])*rstd[j]*slg[c] + slb[c];
            float bq = bvv[k][j];
            float sb = 1.f/(1.f + expf(-(bq*bq*av[j])));
            r[j] = y*sb;
        }
        float4 wr = revout ? make_float4(r[3], r[2], r[1], r[0])
                           : make_float4(r[0], r[1], r[2], r[3]);
        *(float4*)(outb + (size_t)c*HT + obase) = wr;
    }
}

// ---------------- host orchestration --------------------------------------------
#define PW_SMEM   49152
#define PWS_SMEM  57344
#define CB_SMEM   66560

static void run_half(const float* in, float* outb, int rev,
                     const float* dwdw, const float* Wt_b1, const float* Wt_b2,
                     const float* dwg, const float* dwb,
                     const float* caw1, const float* caw2, const float* saw,
                     const float* d1dw, const float* Wt_cb, const float* d1g, const float* d1b,
                     const float* sD, const float* lng, const float* lnb,
                     const float* psc_half,
                     float* bufB, float* bufC, float* bufD,
                     float* pach, float* pcps, float* pcpm, float* psp, float* pasp)
{
    dim3 g5((TT+63)/64, (HH+15)/16, BB*CC);
    dw5_dual2<<<g5, 256>>>(in, dwdw, dwdw + CC*25, bufB, bufC, rev);

    dim3 gp(NBLK, BB);
    pw2<1,false,true ><<<gp, 256, PW_SMEM>>>(bufB, Wt_b1, dwg,    dwb,    bufB, nullptr, pcps, pcpm);
    pw2<1,true ,false><<<gp, 256, PWS_SMEM>>>(bufC, Wt_b2, dwg+CC, dwb+CC, bufC, psp, nullptr, nullptr);

    chan_attn2<<<BB, 256>>>(pcps, pcpm, caw1, caw2, pach);

    cb_fused<<<gp, 256, CB_SMEM>>>(bufB, pach, d1dw, Wt_cb, d1g, d1b, bufD);

    spat_conv<<<dim3((TT+31)/32, (HH+7)/8, BB), dim3(32, 8)>>>(psp, saw, pasp);

    final_fuse<<<gp, 256>>>(bufD, bufC, pasp, psc_half, sD, lng, lnb, outb, rev);
}

extern "C" void kernel_launch(void* const* d_in, const int* in_sizes, int n_in,
                              void* d_out, int out_size)
{
    const float* x       = (const float*)d_in[0];
    const float* in_w    = (const float*)d_in[1];
    const float* dw2d_dw = (const float*)d_in[2];
    const float* dw2d_pw = (const float*)d_in[3];
    const float* dw2d_g  = (const float*)d_in[4];
    const float* dw2d_b  = (const float*)d_in[5];
    const float* ca_w1   = (const float*)d_in[6];
    const float* ca_w2   = (const float*)d_in[7];
    const float* sa_w    = (const float*)d_in[8];
    const float* dw1d_dw = (const float*)d_in[9];
    const float* dw1d_pw = (const float*)d_in[10];
    const float* dw1d_g  = (const float*)d_in[11];
    const float* dw1d_b  = (const float*)d_in[12];
    const float* ssm_A   = (const float*)d_in[13];
    const float* ssm_B   = (const float*)d_in[14];
    const float* ssm_C   = (const float*)d_in[15];
    const float* ssm_D   = (const float*)d_in[16];
    const float* ln_g    = (const float*)d_in[17];
    const float* ln_b    = (const float*)d_in[18];
    const float* out_w   = (const float*)d_in[19];
    const float* out_g   = (const float*)d_in[20];
    const float* out_b   = (const float*)d_in[21];

    float *pA, *pB, *pC, *pD, *pE, *pach, *pcps, *pcpm, *psp, *pasp, *psc, *pWt;
    cudaGetSymbolAddress((void**)&pA,   g_A);
    cudaGetSymbolAddress((void**)&pB,   g_B2);
    cudaGetSymbolAddress((void**)&pC,   g_C2);
    cudaGetSymbolAddress((void**)&pD,   g_D2);
    cudaGetSymbolAddress((void**)&pE,   g_E2);
    cudaGetSymbolAddress((void**)&pach, g_ach);
    cudaGetSymbolAddress((void**)&pcps, g_cps);
    cudaGetSymbolAddress((void**)&pcpm, g_cpm);
    cudaGetSymbolAddress((void**)&psp,  g_sp);
    cudaGetSymbolAddress((void**)&pasp, g_asp);
    cudaGetSymbolAddress((void**)&psc,  g_sc);
    cudaGetSymbolAddress((void**)&pWt,  g_Wt);

    cudaFuncSetAttribute(pw2<0,false,false>, cudaFuncAttributeMaxDynamicSharedMemorySize, PW_SMEM);
    cudaFuncSetAttribute(pw2<1,false,false>, cudaFuncAttributeMaxDynamicSharedMemorySize, PW_SMEM);
    cudaFuncSetAttribute(pw2<1,false,true >, cudaFuncAttributeMaxDynamicSharedMemorySize, PW_SMEM);
    cudaFuncSetAttribute(pw2<1,true ,false>, cudaFuncAttributeMaxDynamicSharedMemorySize, PWS_SMEM);
    cudaFuncSetAttribute(cb_fused,           cudaFuncAttributeMaxDynamicSharedMemorySize, CB_SMEM);
    cudaFuncSetAttribute(ssm_pre3,           cudaFuncAttributeMaxDynamicSharedMemorySize, SSM_SMEM);

    // transpose all 8 pointwise weight matrices; SSM tables
    wtrans<<<8, 256>>>(in_w, dw2d_pw, dw1d_pw, out_w, pWt);
    ssm_pre3<<<2, 256, SSM_SMEM>>>(ssm_A, ssm_B, ssm_C, psc);

    dim3 gp(NBLK, BB);

    // input pointwise mix
    pw2<0,false,false><<<gp, 256, PW_SMEM>>>(x, pWt, nullptr, nullptr, pA, nullptr, nullptr, nullptr);

    // half 1
    run_half(pA, pE, 0,
             dw2d_dw, pWt + 1*CC*CC, pWt + 2*CC*CC, dw2d_g, dw2d_b,
             ca_w1, ca_w2, sa_w,
             dw1d_dw, pWt + 5*CC*CC, dw1d_g, dw1d_b,
             ssm_D, ln_g, ln_b, psc,
             pB, pC, pD, pach, pcps, pcpm, psp, pasp);

    // half 2 (reversed read, reversed write-back)
    run_half(pE, pA, 1,
             dw2d_dw + 2*CC*25, pWt + 3*CC*CC, pWt + 4*CC*CC, dw2d_g + 2*CC, dw2d_b + 2*CC,
             ca_w1 + MIDC*CC, ca_w2 + CC*MIDC, sa_w + 2*49,
             dw1d_dw + CC*3, pWt + 6*CC*CC, dw1d_g + CC, dw1d_b + CC,
             ssm_D + CC, ln_g + CC, ln_b + CC, psc + TT*CC,
             pB, pC, pD, pach, pcps, pcpm, psp, pasp);

    // output pointwise mix + bn + relu
    pw2<1,false,false><<<gp, 256, PW_SMEM>>>(pA, pWt + 7*CC*CC, out_g, out_b, (float*)d_out, nullptr, nullptr, nullptr);
}

// round 13
// speedup vs baseline: 1.0255x; 1.0255x over previous
#include <cuda_runtime.h>
#include <math.h>
#include <float.h>

#define BB 8
#define CC 64
#define HH 62
#define TT 400
#define HT (HH*TT)            // 24800
#define NTOT (BB*CC*HT)       // 12697600
#define SSZ 32
#define MIDC 4
#define NBLK 194              // ceil(HT/128)

typedef unsigned long long u64;

__device__ __forceinline__ u64 ffma2(u64 a, u64 b, u64 c) {
    u64 d;
    asm("fma.rn.f32x2 %0, %1, %2, %3;" : "=l"(d) : "l"(a), "l"(b), "l"(c));
    return d;
}
__device__ __forceinline__ u64 bcast2(float x) {
    u64 r;
    asm("mov.b64 %0, {%1, %1};" : "=l"(r) : "f"(x));
    return r;
}
__device__ __forceinline__ u64 pack2(float lo, float hi) {
    u64 r;
    asm("mov.b64 %0, {%1, %2};" : "=l"(r) : "f"(lo), "f"(hi));
    return r;
}
__device__ __forceinline__ void unpack2(u64 v, float& lo, float& hi) {
    asm("mov.b64 {%0, %1}, %2;" : "=f"(lo), "=f"(hi) : "l"(v));
}

// ---------------- scratch (device globals) ----------------
__device__ float g_A[NTOT];
__device__ float g_B2[NTOT];
__device__ float g_C2[NTOT];
__device__ float g_E2[NTOT];
__device__ float g_ach[BB*CC];
__device__ float g_cps[BB*NBLK*CC];
__device__ float g_cpm[BB*NBLK*CC];
__device__ float g_sp[BB*2*HT];
__device__ float g_asp[BB*HT];
__device__ float g_sc[2*TT*CC];
__device__ float g_Wt[8*CC*CC];       // transposed weights [m][c][o]

// ---------------- transpose all 8 pointwise weight matrices --------------------
__global__ void wtrans(const float* __restrict__ in_w, const float* __restrict__ dwpw,
                       const float* __restrict__ d1pw, const float* __restrict__ out_w,
                       float* __restrict__ Wt)
{
    int m = blockIdx.x;
    const float* src = (m == 0) ? in_w
                     : (m < 5)  ? dwpw + (m-1)*CC*CC
                     : (m < 7)  ? d1pw + (m-5)*CC*CC
                                : out_w;
    for (int i = threadIdx.x; i < CC*CC; i += 256) {
        int o = i >> 6, c = i & 63;
        Wt[m*CC*CC + c*CC + o] = src[i];
    }
}

// ============ register-blocked pointwise 64x64 mix, f32x2 over out-pairs ======
template<int ACT, bool SPSTATS, bool CPARTS>
__launch_bounds__(256, 3)
__global__ void pw2(const float* __restrict__ in, const float* __restrict__ Wt,
                    const float* __restrict__ gamma, const float* __restrict__ beta,
                    float* __restrict__ out, float* __restrict__ sp,
                    float* __restrict__ cps, float* __restrict__ cpm)
{
    extern __shared__ float sm[];
    float* sWt = sm;                   // 4096 floats, [c][o]
    float* sx  = sm + 4096;            // 64*128 floats
    float* sredS = sm + 4096 + 8192;   // 8*128 (SPSTATS)
    float* sredM = sredS + 1024;

    int tid = threadIdx.x;
    int px = tid & 31, oy = tid >> 5;
    int b = blockIdx.y;
    int pos0 = blockIdx.x * 128;
    const float* inb = in + (size_t)b*CC*HT;

    #pragma unroll
    for (int i = tid; i < 1024; i += 256)
        ((float4*)sWt)[i] = ((const float4*)Wt)[i];

    #pragma unroll
    for (int i = tid; i < 2048; i += 256) {
        int c = i >> 5, j = i & 31;
        int gp = pos0 + j*4;
        float4 v = make_float4(0.f,0.f,0.f,0.f);
        if (gp + 3 < HT) {
            v = *(const float4*)(inb + (size_t)c*HT + gp);
        } else {
            float tmp[4] = {0,0,0,0};
            for (int k = 0; k < 4; k++) if (gp+k < HT) tmp[k] = inb[(size_t)c*HT + gp + k];
            v = make_float4(tmp[0],tmp[1],tmp[2],tmp[3]);
        }
        *(float4*)(sx + c*128 + j*4) = v;
    }
    __syncthreads();

    int p = px*4;
    u64 acc2[4][4];
    #pragma unroll
    for (int q = 0; q < 4; q++)
        #pragma unroll
        for (int k = 0; k < 4; k++) acc2[q][k] = 0ull;

    #pragma unroll
    for (int c4 = 0; c4 < 16; c4++) {
        #pragma unroll
        for (int cc = 0; cc < 4; cc++) {
            int c = c4*4 + cc;
            float4 xv = *(const float4*)(sx + c*128 + p);
            u64 xp0 = bcast2(xv.x), xp1 = bcast2(xv.y);
            u64 xp2 = bcast2(xv.z), xp3 = bcast2(xv.w);
            const ulonglong2* wrow = (const ulonglong2*)(sWt + c*64 + oy*8);
            ulonglong2 wa = wrow[0];
            ulonglong2 wb = wrow[1];
            acc2[0][0] = ffma2(wa.x, xp0, acc2[0][0]);
            acc2[0][1] = ffma2(wa.x, xp1, acc2[0][1]);
            acc2[0][2] = ffma2(wa.x, xp2, acc2[0][2]);
            acc2[0][3] = ffma2(wa.x, xp3, acc2[0][3]);
            acc2[1][0] = ffma2(wa.y, xp0, acc2[1][0]);
            acc2[1][1] = ffma2(wa.y, xp1, acc2[1][1]);
            acc2[1][2] = ffma2(wa.y, xp2, acc2[1][2]);
            acc2[1][3] = ffma2(wa.y, xp3, acc2[1][3]);
            acc2[2][0] = ffma2(wb.x, xp0, acc2[2][0]);
            acc2[2][1] = ffma2(wb.x, xp1, acc2[2][1]);
            acc2[2][2] = ffma2(wb.x, xp2, acc2[2][2]);
            acc2[2][3] = ffma2(wb.x, xp3, acc2[2][3]);
            acc2[3][0] = ffma2(wb.y, xp0, acc2[3][0]);
            acc2[3][1] = ffma2(wb.y, xp1, acc2[3][1]);
            acc2[3][2] = ffma2(wb.y, xp2, acc2[3][2]);
            acc2[3][3] = ffma2(wb.y, xp3, acc2[3][3]);
        }
    }

    float rr[8][4];
    #pragma unroll
    for (int q = 0; q < 4; q++)
        #pragma unroll
        for (int k = 0; k < 4; k++)
            unpack2(acc2[q][k], rr[2*q][k], rr[2*q+1][k]);

    int gp0 = pos0 + p;
    bool full = (gp0 + 3) < HT;
    float* outb = out + (size_t)b*CC*HT;
    float psum[4] = {0,0,0,0};
    float pmax[4] = {-FLT_MAX,-FLT_MAX,-FLT_MAX,-FLT_MAX};
    #pragma unroll
    for (int o8 = 0; o8 < 8; o8++) {
        int o = oy*8 + o8;
        float r[4];
        #pragma unroll
        for (int k = 0; k < 4; k++) r[k] = rr[o8][k];
        if (gamma) {
            float g = __ldg(gamma + o), be = __ldg(beta + o);
            #pragma unroll
            for (int k = 0; k < 4; k++) r[k] = fmaf(r[k], g, be);
        }
        #pragma unroll
        for (int k = 0; k < 4; k++) {
            if (ACT == 1) r[k] = fmaxf(r[k], 0.f);
            if (ACT == 2) r[k] = 1.f/(1.f + expf(-r[k]));
        }
        if (SPSTATS) {
            #pragma unroll
            for (int k = 0; k < 4; k++) { psum[k] += r[k]; pmax[k] = fmaxf(pmax[k], r[k]); }
        }
        if (CPARTS) {
            float ps = 0.f, pm = -FLT_MAX;
            #pragma unroll
            for (int k = 0; k < 4; k++)
                if (gp0 + k < HT) { ps += r[k]; pm = fmaxf(pm, r[k]); }
            #pragma unroll
            for (int s = 16; s > 0; s >>= 1) {
                ps += __shfl_xor_sync(0xffffffffu, ps, s);
                pm = fmaxf(pm, __shfl_xor_sync(0xffffffffu, pm, s));
            }
            if (px == 0) {
                cps[((size_t)b*NBLK + blockIdx.x)*CC + o] = ps;
                cpm[((size_t)b*NBLK + blockIdx.x)*CC + o] = pm;
            }
        }
        if (full) {
            *(float4*)(outb + (size_t)o*HT + gp0) = make_float4(r[0],r[1],r[2],r[3]);
        } else {
            for (int k = 0; k < 4; k++) if (gp0+k < HT) outb[(size_t)o*HT + gp0 + k] = r[k];
        }
    }

    if (SPSTATS) {
        #pragma unroll
        for (int k = 0; k < 4; k++) { sredS[oy*128 + p + k] = psum[k]; sredM[oy*128 + p + k] = pmax[k]; }
        __syncthreads();
        if (tid < 128) {
            float s = 0.f, m = -FLT_MAX;
            #pragma unroll
            for (int g = 0; g < 8; g++) { s += sredS[g*128 + tid]; m = fmaxf(m, sredM[g*128 + tid]); }
            int gp = pos0 + tid;
            if (gp < HT) {
                sp[(size_t)b*2*HT + gp]      = s*(1.f/CC);
                sp[(size_t)b*2*HT + HT + gp] = m;
            }
        }
    }
}

// ==== MERGED: dw1x3(b1^2*ach) + pw + bn + sigmoid (=cb) + gelu-residual +
//      channel-LN + spatial gate + (reversed) store — one kernel, no cb pass ====
// smem floats: sraw 0..8448 (conv phase) | sWt 0..4096 (overlay after conv)
//              sred 4224..5248 | smu 5248..5376 | srs 5376..5504
//              sD 5504..5568 | slg 5568..5632 | slb 5632..5696 | sx 8448..16640
__launch_bounds__(256, 3)
__global__ void cbf_fused(const float* __restrict__ b1, const float* __restrict__ b2,
                          const float* __restrict__ ach,
                          const float* __restrict__ dw, const float* __restrict__ Wt,
                          const float* __restrict__ gamma, const float* __restrict__ beta,
                          const float* __restrict__ asp, const float* __restrict__ sc,
                          const float* __restrict__ Dv, const float* __restrict__ lg,
                          const float* __restrict__ lb,
                          float* __restrict__ out, int revout)
{
    extern __shared__ float sm[];
    float* sraw = sm;              // 64*132 (conv phase only)
    float* sWt  = sm;              // union (after conv phase), 4096 floats
    float* sred = sm + 4224;       // 8*128
    float* smu  = sm + 5248;       // 128
    float* srs  = sm + 5376;       // 128
    float* sD   = sm + 5504;       // 64
    float* slg  = sm + 5568;       // 64
    float* slb  = sm + 5632;       // 64
    float* sx   = sm + 8448;       // 64*128

    int tid = threadIdx.x;
    int px = tid & 31, oy = tid >> 5;
    int b = blockIdx.y;
    int pos0 = blockIdx.x * 128;
    const float* inb = b1 + (size_t)b*CC*HT;

    // phase A: f = v^2 * a into sraw (positions pos0-1 .. pos0+128)
    for (int i = tid; i < 64*130; i += 256) {
        int c = i / 130, j = i - c*130;
        int gp = pos0 - 1 + j;
        float v = 0.f;
        if (gp >= 0 && gp < HT) v = inb[(size_t)c*HT + gp];
        float a = __ldg(ach + b*CC + c);
        sraw[c*132 + j] = v*v*a;
    }
    __syncthreads();

    // phase B: 1x3 conv along t into sx
    for (int i = tid; i < 8192; i += 256) {
        int c = i >> 7, j = i & 127;
        int gp = pos0 + j;
        float r = 0.f;
        if (gp < HT) {
            int t = gp - (gp/TT)*TT;
            float w0 = __ldg(dw + c*3), w1 = __ldg(dw + c*3 + 1), w2 = __ldg(dw + c*3 + 2);
            r = w1 * sraw[c*132 + j + 1];
            if (t > 0)    r = fmaf(w0, sraw[c*132 + j],     r);
            if (t < TT-1) r = fmaf(w2, sraw[c*132 + j + 2], r);
        }
        sx[c*128 + j] = r;
    }
    __syncthreads();

    // phase C: load W (+LN/D constants) into regions free after conv phase
    #pragma unroll
    for (int i = tid; i < 1024; i += 256)
        ((float4*)sWt)[i] = ((const float4*)Wt)[i];
    if (tid < CC) { sD[tid] = Dv[tid]; slg[tid] = lg[tid]; slb[tid] = lb[tid]; }
    __syncthreads();

    // phase D: pw GEMM (f32x2 over out-pairs)
    int p = px*4;
    u64 acc2[4][4];
    #pragma unroll
    for (int q = 0; q < 4; q++)
        #pragma unroll
        for (int k = 0; k < 4; k++) acc2[q][k] = 0ull;

    #pragma unroll
    for (int c4 = 0; c4 < 16; c4++) {
        #pragma unroll
        for (int cc = 0; cc < 4; cc++) {
            int c = c4*4 + cc;
            float4 xv = *(const float4*)(sx + c*128 + p);
            u64 xp0 = bcast2(xv.x), xp1 = bcast2(xv.y);
            u64 xp2 = bcast2(xv.z), xp3 = bcast2(xv.w);
            const ulonglong2* wrow = (const ulonglong2*)(sWt + c*64 + oy*8);
            ulonglong2 wa = wrow[0];
            ulonglong2 wb = wrow[1];
            acc2[0][0] = ffma2(wa.x, xp0, acc2[0][0]);
            acc2[0][1] = ffma2(wa.x, xp1, acc2[0][1]);
            acc2[0][2] = ffma2(wa.x, xp2, acc2[0][2]);
            acc2[0][3] = ffma2(wa.x, xp3, acc2[0][3]);
            acc2[1][0] = ffma2(wa.y, xp0, acc2[1][0]);
            acc2[1][1] = ffma2(wa.y, xp1, acc2[1][1]);
            acc2[1][2] = ffma2(wa.y, xp2, acc2[1][2]);
            acc2[1][3] = ffma2(wa.y, xp3, acc2[1][3]);
            acc2[2][0] = ffma2(wb.x, xp0, acc2[2][0]);
            acc2[2][1] = ffma2(wb.x, xp1, acc2[2][1]);
            acc2[2][2] = ffma2(wb.x, xp2, acc2[2][2]);
            acc2[2][3] = ffma2(wb.x, xp3, acc2[2][3]);
            acc2[3][0] = ffma2(wb.y, xp0, acc2[3][0]);
            acc2[3][1] = ffma2(wb.y, xp1, acc2[3][1]);
            acc2[3][2] = ffma2(wb.y, xp2, acc2[3][2]);
            acc2[3][3] = ffma2(wb.y, xp3, acc2[3][3]);
        }
    }

    float val[8][4];      // cb -> gelu-residual values
    #pragma unroll
    for (int q = 0; q < 4; q++)
        #pragma unroll
        for (int k = 0; k < 4; k++)
            unpack2(acc2[q][k], val[2*q][k], val[2*q+1][k]);

    // phase E: bn + sigmoid (cb), then gelu-residual with scrambled scan-channel
    int gp0 = pos0 + p;
    bool ok = (gp0 + 3) < HT;      // 4-groups fully in/out (HT % 4 == 0)
    int t = gp0 % TT, h = gp0 / TT;
    const float* scp = sc + t*CC;
    float psum[4] = {0.f, 0.f, 0.f, 0.f};
    #pragma unroll
    for (int o8 = 0; o8 < 8; o8++) {
        int c = oy*8 + o8;
        float g = __ldg(gamma + c), be = __ldg(beta + c);
        int c2 = (h - 2*c) & (CC-1);
        float dv = sD[c2];
        #pragma unroll
        for (int k = 0; k < 4; k++) {
            float cb = 1.f/(1.f + expf(-fmaf(val[o8][k], g, be)));
            float pre = __ldg(scp + k*CC + c2) + cb*dv;
            float gel = 0.5f*pre*(1.f + erff(pre*0.70710678118654752f));
            val[o8][k] = cb + gel;
            psum[k] += val[o8][k];
        }
    }

    // phase F: LN mean/var across the 64 channels per position
    *(float4*)(sred + oy*128 + p) = make_float4(psum[0], psum[1], psum[2], psum[3]);
    __syncthreads();
    if (tid < 128) {
        float s = 0.f;
        #pragma unroll
        for (int g = 0; g < 8; g++) s += sred[g*128 + tid];
        smu[tid] = s*(1.f/CC);
    }
    __syncthreads();
    float mu[4] = {smu[p], smu[p+1], smu[p+2], smu[p+3]};
    float vp[4] = {0.f, 0.f, 0.f, 0.f};
    #pragma unroll
    for (int o8 = 0; o8 < 8; o8++) {
        #pragma unroll
        for (int k = 0; k < 4; k++) {
            float d = val[o8][k] - mu[k];
            vp[k] = fmaf(d, d, vp[k]);
        }
    }
    __syncthreads();
    *(float4*)(sred + oy*128 + p) = make_float4(vp[0], vp[1], vp[2], vp[3]);
    __syncthreads();
    if (tid < 128) {
        float s = 0.f;
        #pragma unroll
        for (int g = 0; g < 8; g++) s += sred[g*128 + tid];
        srs[tid] = rsqrtf(s*(1.f/CC) + 1e-5f);
    }
    __syncthreads();
    if (!ok) return;

    // phase G: LN affine + spatial gate + (reversed) store
    float rstd[4] = {srs[p], srs[p+1], srs[p+2], srs[p+3]};
    float4 a4 = *(const float4*)(asp + (size_t)b*HT + gp0);
    float av[4] = {a4.x, a4.y, a4.z, a4.w};
    const float* b2b = b2 + (size_t)b*CC*HT;
    float* outb = out + (size_t)b*CC*HT;
    int obase = revout ? (h*TT + (TT-4-t)) : gp0;
    #pragma unroll
    for (int o8 = 0; o8 < 8; o8++) {
        int c = oy*8 + o8;
        float4 bv = *(const float4*)(b2b + (size_t)c*HT + gp0);
        float bq[4] = {bv.x, bv.y, bv.z, bv.w};
        float r[4];
        #pragma unroll
        for (int k = 0; k < 4; k++) {
            float y = (val[o8][k]-mu[k])*rstd[k]*slg[c] + slb[c];
            float sb = 1.f/(1.f + expf(-(bq[k]*bq[k]*av[k])));
            r[k] = y*sb;
        }
        float4 wr = revout ? make_float4(r[3], r[2], r[1], r[0])
                           : make_float4(r[0], r[1], r[2], r[3]);
        *(float4*)(outb + (size_t)c*HT + obase) = wr;
    }
}

// ========= dual depthwise 5x5: 64t x 16h tiles, 4 outputs/thread, f32x2 ========
__launch_bounds__(256)
__global__ void dw5_dual2(const float* __restrict__ in, const float* __restrict__ w0,
                          const float* __restrict__ w1,
                          float* __restrict__ out0, float* __restrict__ out1, int rev)
{
    int bc = blockIdx.z;
    int c  = bc & (CC-1);
    __shared__ float tile[20*68];
    __shared__ u64 swp[25];
    int t0 = blockIdx.x*64 - 2;
    int h0 = blockIdx.y*16 - 2;
    const float* base = in + (size_t)bc*HT;
    int tid = threadIdx.x;

    if (tid < 25) swp[tid] = pack2(__ldg(w0 + c*25 + tid), __ldg(w1 + c*25 + tid));

    for (int i = tid; i < 20*68; i += 256) {
        int hh = i / 68, tt = i - hh*68;
        int h = h0 + hh, t = t0 + tt;
        float v = 0.f;
        if (h >= 0 && h < HH && t >= 0 && t < TT) {
            int tr = rev ? (TT-1-t) : t;
            v = base[h*TT + tr];
        }
        tile[i] = v;
    }
    __syncthreads();

    int tt0 = (tid & 15)*4;
    int hh  = tid >> 4;
    int tg  = blockIdx.x*64 + tt0;
    int hg  = blockIdx.y*16 + hh;

    u64 acc[4] = {0ull, 0ull, 0ull, 0ull};
    #pragma unroll
    for (int kh = 0; kh < 5; kh++) {
        const float* row = tile + (hh + kh)*68 + tt0;
        float4 ra = *(const float4*)(row);
        float4 rb = *(const float4*)(row + 4);
        float r[8] = {ra.x, ra.y, ra.z, ra.w, rb.x, rb.y, rb.z, rb.w};
        #pragma unroll
        for (int kw = 0; kw < 5; kw++) {
            u64 w = swp[kh*5 + kw];
            acc[0] = ffma2(w, bcast2(r[kw+0]), acc[0]);
            acc[1] = ffma2(w, bcast2(r[kw+1]), acc[1]);
            acc[2] = ffma2(w, bcast2(r[kw+2]), acc[2]);
            acc[3] = ffma2(w, bcast2(r[kw+3]), acc[3]);
        }
    }

    if (hg >= HH) return;
    float o0[4], o1[4];
    #pragma unroll
    for (int k = 0; k < 4; k++) unpack2(acc[k], o0[k], o1[k]);
    size_t obase = (size_t)bc*HT + hg*TT + tg;
    if (tg + 3 < TT) {
        *(float4*)(out0 + obase) = make_float4(o0[0], o0[1], o0[2], o0[3]);
        *(float4*)(out1 + obase) = make_float4(o1[0], o1[1], o1[2], o1[3]);
    } else {
        for (int k = 0; k < 4; k++) if (tg + k < TT) {
            out0[obase + k] = o0[k];
            out1[obase + k] = o1[k];
        }
    }
}

// ---------------- channel attention: reduce partials + MLP ---------------------
__global__ void chan_attn2(const float* __restrict__ cps, const float* __restrict__ cpm,
                           const float* __restrict__ w1, const float* __restrict__ w2,
                           float* __restrict__ a)
{
    int b = blockIdx.x, tid = threadIdx.x;
    __shared__ float sa[CC], smx[CC], hs[MIDC];
    int c = tid >> 2, q = tid & 3;
    float s = 0.f, m = -FLT_MAX;
    for (int k = q; k < NBLK; k += 4) {
        s += cps[((size_t)b*NBLK + k)*CC + c];
        m = fmaxf(m, cpm[((size_t)b*NBLK + k)*CC + c]);
    }
    s += __shfl_xor_sync(0xffffffffu, s, 1);
    m = fmaxf(m, __shfl_xor_sync(0xffffffffu, m, 1));
    s += __shfl_xor_sync(0xffffffffu, s, 2);
    m = fmaxf(m, __shfl_xor_sync(0xffffffffu, m, 2));
    if (q == 0) { sa[c] = s*(1.f/(float)HT); smx[c] = m; }
    __syncthreads();
    if (tid < MIDC) {
        float ha = 0.f, hm = 0.f;
        for (int k = 0; k < CC; k++) {
            ha = fmaf(sa[k],  w1[tid*CC + k], ha);
            hm = fmaf(smx[k], w1[tid*CC + k], hm);
        }
        hs[tid] = fmaxf(ha, 0.f) + fmaxf(hm, 0.f);
    }
    __syncthreads();
    if (tid < CC) {
        float acc = 0.f;
        #pragma unroll
        for (int j = 0; j < MIDC; j++) acc = fmaf(hs[j], w2[tid*MIDC + j], acc);
        a[b*CC + tid] = 1.f/(1.f + expf(-acc));
    }
}

// ---------------- spatial attention 7x7 conv (2ch->1) + sigmoid -----------------
__global__ void spat_conv(const float* __restrict__ sp, const float* __restrict__ w,
                          float* __restrict__ asp)
{
    int t = blockIdx.x*32 + threadIdx.x;
    int h = blockIdx.y*8  + threadIdx.y;
    int b = blockIdx.z;
    if (t >= TT || h >= HH) return;
    float acc = 0.f;
    #pragma unroll
    for (int ci = 0; ci < 2; ci++) {
        const float* base = sp + ((size_t)b*2 + ci)*HT;
        #pragma unroll
        for (int kh = 0; kh < 7; kh++) {
            int hh = h + kh - 3;
            if (hh < 0 || hh >= HH) continue;
            #pragma unroll
            for (int kw = 0; kw < 7; kw++) {
                int tt = t + kw - 3;
                if (tt < 0 || tt >= TT) continue;
                acc = fmaf(base[hh*TT + tt], __ldg(&w[ci*49 + kh*7 + kw]), acc);
            }
        }
    }
    asp[(size_t)b*HT + h*TT + t] = 1.f/(1.f + expf(-acc));
}

// ---------------- SSM precompute: log-depth chain via A^8 ----------------------
#define SSM_SMEM ((5152 + TT*SSZ)*4)
__launch_bounds__(256)
__global__ void ssm_pre3(const float* __restrict__ A, const float* __restrict__ Bv,
                         const float* __restrict__ Cm, float* __restrict__ sc)
{
    extern __shared__ float sm[];
    float* sA  = sm;
    float* sM  = sm + 1024;
    float* sT  = sm + 2048;
    float* sC  = sm + 3072;
    float* sVV = sm + 5120;
    float* sS  = sm + 5152;

    int half = blockIdx.x;
    A  += half*SSZ*SSZ;
    Bv += half*SSZ;
    Cm += half*SSZ*CC;
    sc += (size_t)half*TT*CC;

    int tid = threadIdx.x;
    int wid = tid >> 5, lid = tid & 31;

    for (int i = tid; i < 1024; i += 256) sA[i] = A[i];
    for (int i = tid; i < 2048; i += 256) sC[i] = Cm[i];
    __syncthreads();
    for (int i = tid; i < 1024; i += 256) {
        int r = i >> 5, c = i & 31;
        float acc = 0.f;
        #pragma unroll
        for (int k = 0; k < 32; k++) acc = fmaf(sA[r*32+k], sA[k*32+c], acc);
        sT[i] = acc;
    }
    __syncthreads();
    for (int i = tid; i < 1024; i += 256) {
        int r = i >> 5, c = i & 31;
        float acc = 0.f;
        #pragma unroll
        for (int k = 0; k < 32; k++) acc = fmaf(sT[r*32+k], sT[k*32+c], acc);
        sM[i] = acc;
    }
    __syncthreads();
    for (int i = tid; i < 1024; i += 256) {
        int r = i >> 5, c = i & 31;
        float acc = 0.f;
        #pragma unroll
        for (int k = 0; k < 32; k++) acc = fmaf(sM[r*32+k], sM[k*32+c], acc);
        sT[i] = acc;
    }
    __syncthreads();

    if (wid == 0) {
        float bv = Bv[lid];
        float Arow[32];
        #pragma unroll
        for (int j = 0; j < 32; j++) Arow[j] = sA[lid*32 + j];
        float x = bv;
        sS[lid] = x;
        #pragma unroll
        for (int k = 1; k < 8; k++) {
            float nx = bv;
            #pragma unroll
            for (int j = 0; j < 32; j++) nx = fmaf(__shfl_sync(0xffffffffu, x, j), Arow[j], nx);
            x = nx;
            sS[k*32 + lid] = x;
        }
        sVV[lid] = x;
    }
    __syncthreads();

    {
        float Mrow[32];
        #pragma unroll
        for (int j = 0; j < 32; j++) Mrow[j] = sT[lid*32 + j];
        float vv = sVV[lid];
        float x = sS[wid*32 + lid];
        for (int n = 1; n < 50; n++) {
            float p0 = vv, p1 = 0.f, p2 = 0.f, p3 = 0.f;
            #pragma unroll
            for (int j = 0; j < 8; j++) {
                p0 = fmaf(__shfl_sync(0xffffffffu, x, j),    Mrow[j],    p0);
                p1 = fmaf(__shfl_sync(0xffffffffu, x, j+8),  Mrow[j+8],  p1);
                p2 = fmaf(__shfl_sync(0xffffffffu, x, j+16), Mrow[j+16], p2);
                p3 = fmaf(__shfl_sync(0xffffffffu, x, j+24), Mrow[j+24], p3);
            }
            x = (p0 + p1) + (p2 + p3);
            sS[(wid + 8*n)*32 + lid] = x;
        }
    }
    __syncthreads();

    for (int i = tid; i < TT*CC; i += 256) {
        int t = i >> 6, c = i & 63;
        float acc = 0.f;
        #pragma unroll
        for (int k = 0; k < 32; k++) acc = fmaf(sS[t*32 + k], sC[k*64 + c], acc);
        sc[i] = acc;
    }
}

// ---------------- host orchestration --------------------------------------------
#define PW_SMEM   49152
#define PWS_SMEM  57344
#define CB_SMEM   66560

static void run_half(const float* in, float* outb, int rev,
                     const float* dwdw, const float* Wt_b1, const float* Wt_b2,
                     const float* dwg, const float* dwb,
                     const float* caw1, const float* caw2, const float* saw,
                     const float* d1dw, const float* Wt_cb, const float* d1g, const float* d1b,
                     const float* sD, const float* lng, const float* lnb,
                     const float* psc_half,
                     float* bufB, float* bufC,
                     float* pach, float* pcps, float* pcpm, float* psp, float* pasp)
{
    dim3 g5((TT+63)/64, (HH+15)/16, BB*CC);
    dw5_dual2<<<g5, 256>>>(in, dwdw, dwdw + CC*25, bufB, bufC, rev);

    dim3 gp(NBLK, BB);
    pw2<1,false,true ><<<gp, 256, PW_SMEM>>>(bufB, Wt_b1, dwg,    dwb,    bufB, nullptr, pcps, pcpm);
    pw2<1,true ,false><<<gp, 256, PWS_SMEM>>>(bufC, Wt_b2, dwg+CC, dwb+CC, bufC, psp, nullptr, nullptr);

    chan_attn2<<<BB, 256>>>(pcps, pcpm, caw1, caw2, pach);
    spat_conv<<<dim3((TT+31)/32, (HH+7)/8, BB), dim3(32, 8)>>>(psp, saw, pasp);

    // merged cb + final stage: reads b1(bufB), b2(bufC), writes half output
    cbf_fused<<<gp, 256, CB_SMEM>>>(bufB, bufC, pach, d1dw, Wt_cb, d1g, d1b,
                                    pasp, psc_half, sD, lng, lnb, outb, rev);
}

extern "C" void kernel_launch(void* const* d_in, const int* in_sizes, int n_in,
                              void* d_out, int out_size)
{
    const float* x       = (const float*)d_in[0];
    const float* in_w    = (const float*)d_in[1];
    const float* dw2d_dw = (const float*)d_in[2];
    const float* dw2d_pw = (const float*)d_in[3];
    const float* dw2d_g  = (const float*)d_in[4];
    const float* dw2d_b  = (const float*)d_in[5];
    const float* ca_w1   = (const float*)d_in[6];
    const float* ca_w2   = (const float*)d_in[7];
    const float* sa_w    = (const float*)d_in[8];
    const float* dw1d_dw = (const float*)d_in[9];
    const float* dw1d_pw = (const float*)d_in[10];
    const float* dw1d_g  = (const float*)d_in[11];
    const float* dw1d_b  = (const float*)d_in[12];
    const float* ssm_A   = (const float*)d_in[13];
    const float* ssm_B   = (const float*)d_in[14];
    const float* ssm_C   = (const float*)d_in[15];
    const float* ssm_D   = (const float*)d_in[16];
    const float* ln_g    = (const float*)d_in[17];
    const float* ln_b    = (const float*)d_in[18];
    const float* out_w   = (const float*)d_in[19];
    const float* out_g   = (const float*)d_in[20];
    const float* out_b   = (const float*)d_in[21];

    float *pA, *pB, *pC, *pE, *pach, *pcps, *pcpm, *psp, *pasp, *psc, *pWt;
    cudaGetSymbolAddress((void**)&pA,   g_A);
    cudaGetSymbolAddress((void**)&pB,   g_B2);
    cudaGetSymbolAddress((void**)&pC,   g_C2);
    cudaGetSymbolAddress((void**)&pE,   g_E2);
    cudaGetSymbolAddress((void**)&pach, g_ach);
    cudaGetSymbolAddress((void**)&pcps, g_cps);
    cudaGetSymbolAddress((void**)&pcpm, g_cpm);
    cudaGetSymbolAddress((void**)&psp,  g_sp);
    cudaGetSymbolAddress((void**)&pasp, g_asp);
    cudaGetSymbolAddress((void**)&psc,  g_sc);
    cudaGetSymbolAddress((void**)&pWt,  g_Wt);

    cudaFuncSetAttribute(pw2<0,false,false>, cudaFuncAttributeMaxDynamicSharedMemorySize, PW_SMEM);
    cudaFuncSetAttribute(pw2<1,false,false>, cudaFuncAttributeMaxDynamicSharedMemorySize, PW_SMEM);
    cudaFuncSetAttribute(pw2<1,false,true >, cudaFuncAttributeMaxDynamicSharedMemorySize, PW_SMEM);
    cudaFuncSetAttribute(pw2<1,true ,false>, cudaFuncAttributeMaxDynamicSharedMemorySize, PWS_SMEM);
    cudaFuncSetAttribute(cbf_fused,          cudaFuncAttributeMaxDynamicSharedMemorySize, CB_SMEM);
    cudaFuncSetAttribute(ssm_pre3,           cudaFuncAttributeMaxDynamicSharedMemorySize, SSM_SMEM);

    // transpose all 8 pointwise weight matrices; SSM tables
    wtrans<<<8, 256>>>(in_w, dw2d_pw, dw1d_pw, out_w, pWt);
    ssm_pre3<<<2, 256, SSM_SMEM>>>(ssm_A, ssm_B, ssm_C, psc);

    dim3 gp(NBLK, BB);

    // input pointwise mix
    pw2<0,false,false><<<gp, 256, PW_SMEM>>>(x, pWt, nullptr, nullptr, pA, nullptr, nullptr, nullptr);

    // half 1
    run_half(pA, pE, 0,
             dw2d_dw, pWt + 1*CC*CC, pWt + 2*CC*CC, dw2d_g, dw2d_b,
             ca_w1, ca_w2, sa_w,
             dw1d_dw, pWt + 5*CC*CC, dw1d_g, dw1d_b,
             ssm_D, ln_g, ln_b, psc,
             pB, pC, pach, pcps, pcpm, psp, pasp);

    // half 2 (reversed read, reversed write-back)
    run_half(pE, pA, 1,
             dw2d_dw + 2*CC*25, pWt + 3*CC*CC, pWt + 4*CC*CC, dw2d_g + 2*CC, dw2d_b + 2*CC,
             ca_w1 + MIDC*CC, ca_w2 + CC*MIDC, sa_w + 2*49,
             dw1d_dw + CC*3, pWt + 6*CC*CC, dw1d_g + CC, dw1d_b + CC,
             ssm_D + CC, ln_g + CC, ln_b + CC, psc + TT*CC,
             pB, pC, pach, pcps, pcpm, psp, pasp);

    // output pointwise mix + bn + relu
    pw2<1,false,false><<<gp, 256, PW_SMEM>>>(pA, pWt + 7*CC*CC, out_g, out_b, (float*)d_out, nullptr, nullptr, nullptr);
}